// round 5
// baseline (speedup 1.0000x reference)
#include <cuda_runtime.h>
#include <math.h>
#include <float.h>

// ---------------------------------------------------------------------------
// Problem constants
// ---------------------------------------------------------------------------
#define BB     2
#define NN     2048
#define QDIM   1024
#define HEADS  16
#define DHEAD  64
#define INNER  1024
#define BHT    (BB*HEADS)          // 32
#define ATT_SCALE 0.125f           // DIM_HEAD^-0.5 = 1/8 (exact power of two)

// ---------------------------------------------------------------------------
// Scratch (device globals: allocation-free, sanctioned by harness rules)
// ---------------------------------------------------------------------------
__device__ float g_q [BHT*DHEAD*NN];   // q  transposed: [bh][d][n], pre-scaled
__device__ float g_kt[BHT*DHEAD*NN];   // k  transposed: [bh][d][n]
__device__ float g_v [BHT*NN*DHEAD];   // v  natural:    [bh][n][d]
__device__ float g_ao[BB*NN*INNER];    // attention out: [b][n][inner]
__device__ float g_maskf[BB*NN];       // canonical mask (1.0 valid / 0.0 masked)

// ---------------------------------------------------------------------------
// Mask canonicalization with dtype detection (bool vs int32 vs float32).
// Only inspects the first 4096 bytes (always in-bounds for any layout).
//   bool   : bytes are 0/1, ~half the bytes at i%4!=0 are nonzero
//   int32  : bytes [v,0,0,0] -> all i%4!=0 bytes are zero, no byte >= 2
//   float32: 1.0f = 00 00 80 3f -> bytes >= 2 present
// ---------------------------------------------------------------------------
__global__ void mask_prep_k(const unsigned char* __restrict__ p)
{
    __shared__ int flg[2];
    if (threadIdx.x == 0) { flg[0] = 0; flg[1] = 0; }
    __syncthreads();
    int ge2 = 0, offnz = 0;
    for (int i = threadIdx.x; i < BB*NN; i += blockDim.x) {
        unsigned char v = p[i];
        if (v >= 2)        ge2 = 1;
        if ((i & 3) && v)  offnz = 1;
    }
    if (ge2)   atomicOr(&flg[0], 1);
    if (offnz) atomicOr(&flg[1], 1);
    __syncthreads();
    const int mode = flg[0] ? 2 : (flg[1] ? 0 : 1);   // 2=f32, 0=bool/int8, 1=int32
    for (int i = threadIdx.x; i < BB*NN; i += blockDim.x) {
        float f;
        if (mode == 0)      f = p[i] ? 1.f : 0.f;
        else if (mode == 1) f = ((const int*)p)[i] ? 1.f : 0.f;
        else                f = (((const float*)p)[i] != 0.f) ? 1.f : 0.f;
        g_maskf[i] = f;
    }
}

// ---------------------------------------------------------------------------
// Generic 128x128x(K=1024) fp32 SGEMM, 256 threads, 8x8 micro-tile,
// register-double-buffered global loads. Epilogue mode:
//   mode 0: C = x@Wq   -> g_q  [bh][d][n], scaled by ATT_SCALE
//   mode 1: C = x@Wkv  -> cols <1024: g_kt [bh][d][n]; cols >=1024: g_v [bh][n][d]
//   mode 2: C = g_ao@Wo + bo -> outp [m][c]   (A argument ignored)
// ---------------------------------------------------------------------------
__global__ __launch_bounds__(256) void sgemm_k(
    const float* __restrict__ A, const float* __restrict__ W,
    int Ncols, int mode, const float* __restrict__ bvec, float* __restrict__ outp)
{
    __shared__ float As[8][132];   // [kk][m], padded (132*4 = 528 = 33*16, float4-safe)
    __shared__ float Ws[8][128];   // [kk][n]

    const int tid  = threadIdx.x;
    const int tx   = tid & 15;
    const int ty   = tid >> 4;
    const int row0 = blockIdx.y * 128;
    const int col0 = blockIdx.x * 128;

    const float* Ap = (mode == 2) ? g_ao : A;

    const int am = tid >> 1;          // 0..127  A tile row
    const int ak = (tid & 1) * 4;     // 0 or 4  A tile k-offset
    const int wk = tid >> 5;          // 0..7    W tile row (k)
    const int wn = (tid & 31) * 4;    // 0..124  W tile col

    const float* aptr = Ap + (size_t)(row0 + am) * QDIM + ak;
    const float* wptr = W  + (size_t)wk * Ncols + col0 + wn;

    float4 pa = *(const float4*)aptr;
    float4 pw = *(const float4*)wptr;

    float acc[8][8];
    #pragma unroll
    for (int i = 0; i < 8; i++)
        #pragma unroll
        for (int j = 0; j < 8; j++) acc[i][j] = 0.f;

    const int NT = QDIM / 8;   // 128 k-tiles
    for (int t = 0; t < NT; t++) {
        As[ak+0][am] = pa.x; As[ak+1][am] = pa.y;
        As[ak+2][am] = pa.z; As[ak+3][am] = pa.w;
        *(float4*)&Ws[wk][wn] = pw;
        __syncthreads();
        if (t + 1 < NT) {
            pa = *(const float4*)(aptr + (t+1)*8);
            pw = *(const float4*)(wptr + (size_t)(t+1)*8*Ncols);
        }
        #pragma unroll
        for (int kk = 0; kk < 8; kk++) {
            float4 a0 = *(const float4*)&As[kk][ty*4];
            float4 a1 = *(const float4*)&As[kk][64 + ty*4];
            float4 b0 = *(const float4*)&Ws[kk][tx*4];
            float4 b1 = *(const float4*)&Ws[kk][64 + tx*4];
            float ar[8] = {a0.x,a0.y,a0.z,a0.w,a1.x,a1.y,a1.z,a1.w};
            float br[8] = {b0.x,b0.y,b0.z,b0.w,b1.x,b1.y,b1.z,b1.w};
            #pragma unroll
            for (int i = 0; i < 8; i++)
                #pragma unroll
                for (int j = 0; j < 8; j++)
                    acc[i][j] += ar[i] * br[j];
        }
        __syncthreads();
    }

    // Epilogue
    #pragma unroll
    for (int i = 0; i < 8; i++) {
        const int r = row0 + ((i < 4) ? (ty*4 + i) : (64 + ty*4 + i - 4));
        const int b = r >> 11;       // / 2048
        const int n = r & 2047;
        #pragma unroll
        for (int j = 0; j < 8; j++) {
            const int c = col0 + ((j < 4) ? (tx*4 + j) : (64 + tx*4 + j - 4));
            const float v = acc[i][j];
            if (mode == 0) {
                const int h = c >> 6, d = c & 63;
                g_q[((size_t)((b*HEADS + h)*DHEAD + d))*NN + n] = v * ATT_SCALE;
            } else if (mode == 1) {
                if (c < INNER) {
                    const int h = c >> 6, d = c & 63;
                    g_kt[((size_t)((b*HEADS + h)*DHEAD + d))*NN + n] = v;
                } else {
                    const int c2 = c - INNER;
                    const int h = c2 >> 6, d = c2 & 63;
                    g_v[((size_t)((b*HEADS + h)*NN + n))*DHEAD + d] = v;
                }
            } else {
                outp[(size_t)r * INNER + c] = v + bvec[c];
            }
        }
    }
}

// ---------------------------------------------------------------------------
// Flash attention: one CTA = 64 query rows of one (b,h). 256 threads,
// 4x4 micro-tiles over [64 q x 64 k] S-tiles, online softmax, O accumulated
// in registers, written directly in [b][n][inner] layout.
// ---------------------------------------------------------------------------
#define LDK 68                      // padded row length for Ks/Vs/Ps

__global__ __launch_bounds__(256) void attn_k(const float* __restrict__ bias)
{
    extern __shared__ float sm[];
    float* Qs = sm;                    // [64][64]  (d-major: Qs[d][q])
    float* Ks = Qs + 64*64;            // [64][LDK] (d-major: Ks[d][k])
    float* Vs = Ks + 64*LDK;           // [64][LDK] (k-major: Vs[k][d])
    float* Ps = Vs + 64*LDK;           // [64][LDK] (Ps[q][k])

    const int tid = threadIdx.x;
    const int tx  = tid & 15;
    const int ty  = tid >> 4;
    const int b   = blockIdx.z;
    const int h   = blockIdx.y;
    const int q0  = blockIdx.x * 64;
    const int bh  = b*HEADS + h;

    // Load Q tile (already transposed & scaled in gmem): Qs[d][q]
    {
        const int d  = tid >> 2;
        const int qc = (tid & 3) * 16;
        const float* src = g_q + ((size_t)(bh*DHEAD + d))*NN + q0 + qc;
        float* dst = Qs + d*64 + qc;
        #pragma unroll
        for (int c = 0; c < 4; c++)
            *(float4*)(dst + c*4) = *(const float4*)(src + c*4);
    }

    float o[4][4];
    float m_run[4], l_run[4];
    #pragma unroll
    for (int ii = 0; ii < 4; ii++) {
        m_run[ii] = -INFINITY;
        l_run[ii] = 0.f;
        #pragma unroll
        for (int jj = 0; jj < 4; jj++) o[ii][jj] = 0.f;
    }

    for (int k0 = 0; k0 < NN; k0 += 64) {
        __syncthreads();   // previous iteration done with Ks/Vs/Ps (and Qs store done)
        // Load K^T tile [d][k] and V tile [k][d]
        {
            const int r  = tid >> 2;
            const int cc = (tid & 3) * 16;
            const float* ksrc = g_kt + ((size_t)(bh*DHEAD + r))*NN + k0 + cc;
            const float* vsrc = g_v  + ((size_t)(bh*NN + k0 + r))*DHEAD + cc;
            float* kd = Ks + r*LDK + cc;
            float* vd = Vs + r*LDK + cc;
            #pragma unroll
            for (int c = 0; c < 4; c++) {
                *(float4*)(kd + c*4) = *(const float4*)(ksrc + c*4);
                *(float4*)(vd + c*4) = *(const float4*)(vsrc + c*4);
            }
        }
        // Bias tile + mask flags straight to registers (coalesced, L2-resident)
        float br[4][4], mk[4];
        #pragma unroll
        for (int ii = 0; ii < 4; ii++) {
            float4 t = *(const float4*)(bias + ((size_t)(b*NN + q0 + ty*4 + ii))*NN + k0 + tx*4);
            br[ii][0] = t.x; br[ii][1] = t.y; br[ii][2] = t.z; br[ii][3] = t.w;
        }
        #pragma unroll
        for (int jj = 0; jj < 4; jj++)
            mk[jj] = g_maskf[b*NN + k0 + tx*4 + jj];
        __syncthreads();

        // S = (Q*scale) @ K^T
        float s[4][4];
        #pragma unroll
        for (int ii = 0; ii < 4; ii++)
            #pragma unroll
            for (int jj = 0; jj < 4; jj++) s[ii][jj] = 0.f;
        #pragma unroll 16
        for (int d = 0; d < 64; d++) {
            float4 qa = *(const float4*)(Qs + d*64  + ty*4);
            float4 kb = *(const float4*)(Ks + d*LDK + tx*4);
            float ar[4] = {qa.x, qa.y, qa.z, qa.w};
            float cr[4] = {kb.x, kb.y, kb.z, kb.w};
            #pragma unroll
            for (int ii = 0; ii < 4; ii++)
                #pragma unroll
                for (int jj = 0; jj < 4; jj++)
                    s[ii][jj] += ar[ii] * cr[jj];
        }

        // bias + mask + online softmax (row reductions across 16-lane half-warps)
        #pragma unroll
        for (int ii = 0; ii < 4; ii++) {
            float sv[4];
            #pragma unroll
            for (int jj = 0; jj < 4; jj++) {
                float v = s[ii][jj] + br[ii][jj];
                sv[jj] = (mk[jj] != 0.f) ? v : -FLT_MAX;
            }
            float rm = fmaxf(fmaxf(sv[0], sv[1]), fmaxf(sv[2], sv[3]));
            #pragma unroll
            for (int off = 1; off < 16; off <<= 1)
                rm = fmaxf(rm, __shfl_xor_sync(0xffffffffu, rm, off));
            const float mn   = fmaxf(m_run[ii], rm);
            const float corr = __expf(m_run[ii] - mn);
            float p[4];
            #pragma unroll
            for (int jj = 0; jj < 4; jj++) p[jj] = __expf(sv[jj] - mn);
            float rs = p[0] + p[1] + p[2] + p[3];
            #pragma unroll
            for (int off = 1; off < 16; off <<= 1)
                rs += __shfl_xor_sync(0xffffffffu, rs, off);
            l_run[ii] = l_run[ii] * corr + rs;
            m_run[ii] = mn;
            #pragma unroll
            for (int jj = 0; jj < 4; jj++) o[ii][jj] *= corr;
            *(float4*)(Ps + (ty*4 + ii)*LDK + tx*4) = make_float4(p[0], p[1], p[2], p[3]);
        }
        __syncthreads();

        // O += P @ V
        #pragma unroll 16
        for (int j = 0; j < 64; j++) {
            float4 vv = *(const float4*)(Vs + j*LDK + tx*4);
            float vr[4] = {vv.x, vv.y, vv.z, vv.w};
            #pragma unroll
            for (int ii = 0; ii < 4; ii++) {
                const float pv = Ps[(ty*4 + ii)*LDK + j];
                #pragma unroll
                for (int jj = 0; jj < 4; jj++)
                    o[ii][jj] += pv * vr[jj];
            }
        }
    }

    // Normalize and write O in [b][n][inner] layout
    #pragma unroll
    for (int ii = 0; ii < 4; ii++) {
        const float inv = 1.0f / l_run[ii];
        float4 r = make_float4(o[ii][0]*inv, o[ii][1]*inv, o[ii][2]*inv, o[ii][3]*inv);
        *(float4*)(g_ao + ((size_t)(b*NN + q0 + ty*4 + ii))*INNER + h*DHEAD + tx*4) = r;
    }
}

// ---------------------------------------------------------------------------
// Launch: x, bias, mask, Wq, Wkv, Wo, bo  (setup_inputs order)
// ---------------------------------------------------------------------------
extern "C" void kernel_launch(void* const* d_in, const int* in_sizes, int n_in,
                              void* d_out, int out_size)
{
    const float*         x    = (const float*)d_in[0];
    const float*         bias = (const float*)d_in[1];
    const unsigned char* mask = (const unsigned char*)d_in[2];
    const float*         Wq   = (const float*)d_in[3];
    const float*         Wkv  = (const float*)d_in[4];
    const float*         Wo   = (const float*)d_in[5];
    const float*         bo   = (const float*)d_in[6];
    float*               out  = (float*)d_out;

    const int attn_smem = (64*64 + 3*64*LDK) * (int)sizeof(float);   // 68608 B
    cudaFuncSetAttribute(attn_k, cudaFuncAttributeMaxDynamicSharedMemorySize, attn_smem);

    mask_prep_k<<<1, 256>>>(mask);
    sgemm_k<<<dim3(INNER/128,   (BB*NN)/128), 256>>>(x, Wq,  INNER,   0, nullptr, nullptr);
    sgemm_k<<<dim3(2*INNER/128, (BB*NN)/128), 256>>>(x, Wkv, 2*INNER, 1, nullptr, nullptr);
    attn_k<<<dim3(NN/64, HEADS, BB), 256, attn_smem>>>(bias);
    sgemm_k<<<dim3(INNER/128,   (BB*NN)/128), 256>>>(nullptr, Wo, INNER, 2, bo, out);
}

// round 6
// speedup vs baseline: 2.1111x; 2.1111x over previous
#include <cuda_runtime.h>
#include <math.h>
#include <float.h>

// ---------------------------------------------------------------------------
// Problem constants
// ---------------------------------------------------------------------------
#define BB     2
#define NN     2048
#define QDIM   1024
#define HEADS  16
#define DHEAD  64
#define INNER  1024
#define BHT    (BB*HEADS)
#define ATT_SCALE 0.125f

// ---------------------------------------------------------------------------
// Scratch
// ---------------------------------------------------------------------------
__device__ float g_q [BHT*DHEAD*NN];   // q  transposed: [bh][d][n], pre-scaled
__device__ float g_kt[BHT*DHEAD*NN];   // k  transposed: [bh][d][n]
__device__ float g_v [BHT*NN*DHEAD];   // v  natural:    [bh][n][d]
__device__ float g_ao[BB*NN*INNER];    // attention out: [b][n][inner]
__device__ float g_maskf[BB*NN];       // canonical mask

// ---------------------------------------------------------------------------
// Helpers: tf32 convert (rna rounding: unbiased), mma, cp.async
// ---------------------------------------------------------------------------
__device__ __forceinline__ unsigned f2tf(float f) {
    unsigned u; asm("cvt.rna.tf32.f32 %0, %1;" : "=r"(u) : "f"(f)); return u;
}
__device__ __forceinline__ void mma8(float* d, const unsigned* a, unsigned b0, unsigned b1) {
    asm volatile(
        "mma.sync.aligned.m16n8k8.row.col.f32.tf32.tf32.f32 "
        "{%0,%1,%2,%3}, {%4,%5,%6,%7}, {%8,%9}, {%0,%1,%2,%3};\n"
        : "+f"(d[0]), "+f"(d[1]), "+f"(d[2]), "+f"(d[3])
        : "r"(a[0]), "r"(a[1]), "r"(a[2]), "r"(a[3]), "r"(b0), "r"(b1));
}
__device__ __forceinline__ void cpa16(void* sdst, const void* gsrc) {
    unsigned s = (unsigned)__cvta_generic_to_shared(sdst);
    asm volatile("cp.async.cg.shared.global [%0], [%1], 16;\n" :: "r"(s), "l"(gsrc));
}

// ---------------------------------------------------------------------------
// Mask canonicalization (dtype-detecting), unchanged from passing R5 kernel
// ---------------------------------------------------------------------------
__global__ void mask_prep_k(const unsigned char* __restrict__ p)
{
    __shared__ int flg[2];
    if (threadIdx.x == 0) { flg[0] = 0; flg[1] = 0; }
    __syncthreads();
    int ge2 = 0, offnz = 0;
    for (int i = threadIdx.x; i < BB*NN; i += blockDim.x) {
        unsigned char v = p[i];
        if (v >= 2)        ge2 = 1;
        if ((i & 3) && v)  offnz = 1;
    }
    if (ge2)   atomicOr(&flg[0], 1);
    if (offnz) atomicOr(&flg[1], 1);
    __syncthreads();
    const int mode = flg[0] ? 2 : (flg[1] ? 0 : 1);
    for (int i = threadIdx.x; i < BB*NN; i += blockDim.x) {
        float f;
        if (mode == 0)      f = p[i] ? 1.f : 0.f;
        else if (mode == 1) f = ((const int*)p)[i] ? 1.f : 0.f;
        else                f = (((const float*)p)[i] != 0.f) ? 1.f : 0.f;
        g_maskf[i] = f;
    }
}

// ---------------------------------------------------------------------------
// TF32 tensor-core GEMM: CTA 128x128, 4 warps of 64x64, BK=16, cp.async
// double-buffered. K fixed at 1024. Modes identical to R5:
//   0: C = x@Wq  -> g_q [bh][d][n] * SCALE   1: x@Wkv -> g_kt / g_v
//   2: C = g_ao@Wo + bo -> outp
// ---------------------------------------------------------------------------
#define APAD 20
#define BPAD 136
__global__ __launch_bounds__(128) void tgemm_k(
    const float* __restrict__ A, const float* __restrict__ W,
    int Ncols, int mode, const float* __restrict__ bvec, float* __restrict__ outp)
{
    __shared__ float As[2][128][APAD];   // [m][k], pad 20 -> conflict-free A frags
    __shared__ float Bs[2][16][BPAD];    // [k][n], pad 136 -> conflict-free B frags

    const int tid  = threadIdx.x;
    const int lane = tid & 31, wid = tid >> 5;
    const int g = lane >> 2, c = lane & 3;
    const int wm = wid & 1, wn = wid >> 1;          // 2x2 warp grid
    const int row0 = blockIdx.y * 128, col0 = blockIdx.x * 128;

    const float* Ap = (mode == 2) ? g_ao : A;

    float acc[4][8][4];
    #pragma unroll
    for (int mt = 0; mt < 4; mt++)
        #pragma unroll
        for (int nt = 0; nt < 8; nt++)
            #pragma unroll
            for (int j = 0; j < 4; j++) acc[mt][nt][j] = 0.f;

    auto load_stage = [&](int t, int bufi) {
        #pragma unroll
        for (int i = 0; i < 4; i++) {
            int j = tid + 128*i;
            int r = j >> 2, k = (j & 3) * 4;
            cpa16(&As[bufi][r][k], &Ap[(size_t)(row0 + r)*QDIM + t*16 + k]);
        }
        #pragma unroll
        for (int i = 0; i < 4; i++) {
            int j = tid + 128*i;
            int kr = j >> 5, n = (j & 31) * 4;
            cpa16(&Bs[bufi][kr][n], &W[(size_t)(t*16 + kr)*Ncols + col0 + n]);
        }
        asm volatile("cp.async.commit_group;\n");
    };

    load_stage(0, 0);
    const int NT = QDIM / 16;   // 64 stages
    for (int t = 0; t < NT; t++) {
        const int bufi = t & 1;
        if (t + 1 < NT) {
            load_stage(t + 1, bufi ^ 1);
            asm volatile("cp.async.wait_group 1;\n");
        } else {
            asm volatile("cp.async.wait_group 0;\n");
        }
        __syncthreads();

        #pragma unroll
        for (int k8 = 0; k8 < 16; k8 += 8) {
            unsigned af[4][4], bf[8][2];
            #pragma unroll
            for (int mt = 0; mt < 4; mt++) {
                const int r = wm*64 + mt*16;
                af[mt][0] = f2tf(As[bufi][r + g    ][k8 + c    ]);
                af[mt][1] = f2tf(As[bufi][r + g + 8][k8 + c    ]);
                af[mt][2] = f2tf(As[bufi][r + g    ][k8 + c + 4]);
                af[mt][3] = f2tf(As[bufi][r + g + 8][k8 + c + 4]);
            }
            #pragma unroll
            for (int nt = 0; nt < 8; nt++) {
                const int n = wn*64 + nt*8 + g;
                bf[nt][0] = f2tf(Bs[bufi][k8 + c    ][n]);
                bf[nt][1] = f2tf(Bs[bufi][k8 + c + 4][n]);
            }
            #pragma unroll
            for (int mt = 0; mt < 4; mt++)
                #pragma unroll
                for (int nt = 0; nt < 8; nt++)
                    mma8(acc[mt][nt], af[mt], bf[nt][0], bf[nt][1]);
        }
        __syncthreads();
    }

    // Epilogue
    #pragma unroll
    for (int mt = 0; mt < 4; mt++) {
        #pragma unroll
        for (int rr = 0; rr < 2; rr++) {
            const int r = row0 + wm*64 + mt*16 + g + rr*8;
            const int b = r >> 11, n = r & 2047;
            #pragma unroll
            for (int nt = 0; nt < 8; nt++) {
                #pragma unroll
                for (int jj = 0; jj < 2; jj++) {
                    const int cc = col0 + wn*64 + nt*8 + 2*c + jj;
                    const float v = acc[mt][nt][rr*2 + jj];
                    if (mode == 0) {
                        const int h = cc >> 6, d = cc & 63;
                        g_q[((size_t)((b*HEADS + h)*DHEAD + d))*NN + n] = v * ATT_SCALE;
                    } else if (mode == 1) {
                        if (cc < INNER) {
                            const int h = cc >> 6, d = cc & 63;
                            g_kt[((size_t)((b*HEADS + h)*DHEAD + d))*NN + n] = v;
                        } else {
                            const int c2 = cc - INNER;
                            const int h = c2 >> 6, d = c2 & 63;
                            g_v[((size_t)((b*HEADS + h)*NN + n))*DHEAD + d] = v;
                        }
                    } else {
                        outp[(size_t)r * INNER + cc] = v + bvec[cc];
                    }
                }
            }
        }
    }
}

// ---------------------------------------------------------------------------
// TF32 tensor-core flash attention.
// CTA = 64 q-rows x one (b,h), 4 warps each owning 16 q-rows (one m16 tile).
// Q fragments register-resident across the whole key loop.
// ---------------------------------------------------------------------------
#define LDP 72    // pad: frag-load pattern c*72+g is bank-conflict-free
__global__ __launch_bounds__(128) void attn_t(const float* __restrict__ bias)
{
    extern __shared__ float sm[];
    float* Ks = sm;              // [64][72]  [d][key]   (also Q staging [d][q])
    float* Vs = Ks + 64*LDP;     // [64][72]  [key][d]
    float* Ps = Vs + 64*LDP;     // [64][72]  [q][key]
    float* Ms = Ps + 64*LDP;     // [64] mask chunk

    const int tid  = threadIdx.x;
    const int lane = tid & 31, wid = tid >> 5;
    const int g = lane >> 2, c = lane & 3;
    const int b = blockIdx.z, h = blockIdx.y, q0 = blockIdx.x*64;
    const int bh = b*HEADS + h;
    const int qw = wid*16;                         // warp's q offset in tile

    // ---- stage Q [d][q] and build A-fragments (Q pre-scaled in g_q) ----
    #pragma unroll
    for (int i = 0; i < 8; i++) {
        int j = tid + 128*i;                       // 0..1023 float4 idx
        int d = j >> 4, q = (j & 15) * 4;
        *(float4*)&Ks[d*LDP + q] = *(const float4*)&g_q[((size_t)(bh*DHEAD + d))*NN + q0 + q];
    }
    __syncthreads();
    unsigned qa[8][4];
    #pragma unroll
    for (int d8 = 0; d8 < 8; d8++) {
        qa[d8][0] = f2tf(Ks[(d8*8 + c    )*LDP + qw + g    ]);
        qa[d8][1] = f2tf(Ks[(d8*8 + c    )*LDP + qw + g + 8]);
        qa[d8][2] = f2tf(Ks[(d8*8 + c + 4)*LDP + qw + g    ]);
        qa[d8][3] = f2tf(Ks[(d8*8 + c + 4)*LDP + qw + g + 8]);
    }
    __syncthreads();

    float oacc[8][4];
    #pragma unroll
    for (int nt = 0; nt < 8; nt++)
        #pragma unroll
        for (int j = 0; j < 4; j++) oacc[nt][j] = 0.f;
    float mr[2] = {-1.7e38f, -1.7e38f};
    float lr[2] = {0.f, 0.f};

    const float* bias_base = bias + (size_t)(b*NN + q0 + qw)*NN;

    for (int kc = 0; kc < NN/64; kc++) {
        const int k0 = kc*64;
        // ---- load K^T [d][key], V [key][d], mask ----
        #pragma unroll
        for (int i = 0; i < 8; i++) {
            int j = tid + 128*i;
            int r = j >> 4, cc4 = (j & 15) * 4;
            *(float4*)&Ks[r*LDP + cc4] = *(const float4*)&g_kt[((size_t)(bh*DHEAD + r))*NN + k0 + cc4];
            *(float4*)&Vs[r*LDP + cc4] = *(const float4*)&g_v [((size_t)(bh*NN + k0 + r))*DHEAD + cc4];
        }
        if (tid < 64) Ms[tid] = g_maskf[b*NN + k0 + tid];
        __syncthreads();

        // ---- S = Q @ K^T ----
        float sacc[8][4];
        #pragma unroll
        for (int nt = 0; nt < 8; nt++)
            #pragma unroll
            for (int j = 0; j < 4; j++) sacc[nt][j] = 0.f;
        #pragma unroll
        for (int d8 = 0; d8 < 8; d8++) {
            unsigned kb[8][2];
            #pragma unroll
            for (int nt = 0; nt < 8; nt++) {
                kb[nt][0] = f2tf(Ks[(d8*8 + c    )*LDP + nt*8 + g]);
                kb[nt][1] = f2tf(Ks[(d8*8 + c + 4)*LDP + nt*8 + g]);
            }
            #pragma unroll
            for (int nt = 0; nt < 8; nt++)
                mma8(sacc[nt], qa[d8], kb[nt][0], kb[nt][1]);
        }

        // ---- mask regs (per key-col, shared by both rows of the lane) ----
        float mk[16];
        #pragma unroll
        for (int nt = 0; nt < 8; nt++) {
            mk[nt*2    ] = Ms[nt*8 + 2*c    ];
            mk[nt*2 + 1] = Ms[nt*8 + 2*c + 1];
        }

        // ---- bias + mask + online softmax (rows g, g+8 of this lane) ----
        #pragma unroll
        for (int rr = 0; rr < 2; rr++) {
            const float* bp = bias_base + (size_t)(g + rr*8)*NN + k0;
            float sv[16];
            #pragma unroll
            for (int nt = 0; nt < 8; nt++) {
                float2 bb = *(const float2*)&bp[nt*8 + 2*c];
                float v0 = sacc[nt][rr*2    ] + bb.x;
                float v1 = sacc[nt][rr*2 + 1] + bb.y;
                sv[nt*2    ] = (mk[nt*2    ] != 0.f) ? v0 : -3.4e38f;
                sv[nt*2 + 1] = (mk[nt*2 + 1] != 0.f) ? v1 : -3.4e38f;
            }
            float rm = sv[0];
            #pragma unroll
            for (int j = 1; j < 16; j++) rm = fmaxf(rm, sv[j]);
            rm = fmaxf(rm, __shfl_xor_sync(0xffffffffu, rm, 1));
            rm = fmaxf(rm, __shfl_xor_sync(0xffffffffu, rm, 2));
            const float mn   = fmaxf(mr[rr], rm);
            const float corr = __expf(mr[rr] - mn);
            mr[rr] = mn;
            float rs = 0.f;
            #pragma unroll
            for (int j = 0; j < 16; j++) { sv[j] = __expf(sv[j] - mn); rs += sv[j]; }
            rs += __shfl_xor_sync(0xffffffffu, rs, 1);
            rs += __shfl_xor_sync(0xffffffffu, rs, 2);
            lr[rr] = lr[rr]*corr + rs;
            #pragma unroll
            for (int nt = 0; nt < 8; nt++) {
                oacc[nt][rr*2    ] *= corr;
                oacc[nt][rr*2 + 1] *= corr;
                *(float2*)&Ps[(qw + g + rr*8)*LDP + nt*8 + 2*c] = make_float2(sv[nt*2], sv[nt*2+1]);
            }
        }
        // P is produced and consumed by the SAME warp -> no barrier needed.

        // ---- O += P @ V ----
        #pragma unroll
        for (int k8 = 0; k8 < 8; k8++) {
            unsigned pa[4];
            pa[0] = f2tf(Ps[(qw + g    )*LDP + k8*8 + c    ]);
            pa[1] = f2tf(Ps[(qw + g + 8)*LDP + k8*8 + c    ]);
            pa[2] = f2tf(Ps[(qw + g    )*LDP + k8*8 + c + 4]);
            pa[3] = f2tf(Ps[(qw + g + 8)*LDP + k8*8 + c + 4]);
            #pragma unroll
            for (int nt = 0; nt < 8; nt++) {
                unsigned vb0 = f2tf(Vs[(k8*8 + c    )*LDP + nt*8 + g]);
                unsigned vb1 = f2tf(Vs[(k8*8 + c + 4)*LDP + nt*8 + g]);
                mma8(oacc[nt], pa, vb0, vb1);
            }
        }
        __syncthreads();   // before next chunk overwrites Ks/Vs
    }

    // ---- normalize + write O in [b][n][inner] ----
    #pragma unroll
    for (int rr = 0; rr < 2; rr++) {
        const float inv = 1.0f / lr[rr];
        const int qg = q0 + qw + g + rr*8;
        float* op = g_ao + (size_t)(b*NN + qg)*INNER + h*DHEAD;
        #pragma unroll
        for (int nt = 0; nt < 8; nt++)
            *(float2*)&op[nt*8 + 2*c] =
                make_float2(oacc[nt][rr*2]*inv, oacc[nt][rr*2+1]*inv);
    }
}

// ---------------------------------------------------------------------------
// Launch: x, bias, mask, Wq, Wkv, Wo, bo
// ---------------------------------------------------------------------------
extern "C" void kernel_launch(void* const* d_in, const int* in_sizes, int n_in,
                              void* d_out, int out_size)
{
    const float*         x    = (const float*)d_in[0];
    const float*         bias = (const float*)d_in[1];
    const unsigned char* mask = (const unsigned char*)d_in[2];
    const float*         Wq   = (const float*)d_in[3];
    const float*         Wkv  = (const float*)d_in[4];
    const float*         Wo   = (const float*)d_in[5];
    const float*         bo   = (const float*)d_in[6];
    float*               out  = (float*)d_out;

    const int attn_smem = (3*64*LDP + 64) * (int)sizeof(float);   // 55552 B
    cudaFuncSetAttribute(attn_t, cudaFuncAttributeMaxDynamicSharedMemorySize, attn_smem);

    mask_prep_k<<<1, 256>>>(mask);
    tgemm_k<<<dim3(INNER/128,   (BB*NN)/128), 128>>>(x, Wq,  INNER,   0, nullptr, nullptr);
    tgemm_k<<<dim3(2*INNER/128, (BB*NN)/128), 128>>>(x, Wkv, 2*INNER, 1, nullptr, nullptr);
    attn_t<<<dim3(NN/64, HEADS, BB), 128, attn_smem>>>(bias);
    tgemm_k<<<dim3(INNER/128,   (BB*NN)/128), 128>>>(nullptr, Wo, INNER, 2, bo, out);
}